// round 15
// baseline (speedup 1.0000x reference)
#include <cuda_runtime.h>
#include <cuda_fp16.h>
#include <math.h>
#include <float.h>
#include <stdint.h>

// ---------------- problem constants ----------------
#define DIMX 2048
#define NSEQ 2048
#define BATCH 2
#define HEADS 16
#define DHEAD 64
#define ROWS (BATCH*NSEQ)          // 4096
#define AINNER 1024
#define FFINNER 8192
#define FUSEDC 17536
#define FPAD2 17536                // [Q 1024 | K 64 | V 64 | ff pairs 16384]
#define JK 1024
#define JV 1088
#define JFF 1152
#define I2 1152
#define KC 9216                    // combined K: 1024 (attn) + 8192 (ff)
#define KOFF 1024

// ---------------- scratch (device globals) --------
__device__ __align__(16) __half g_XN16[(size_t)ROWS*DIMX];
__device__ __align__(16) __half g_WF16[(size_t)FPAD2*DIMX];    // [n][k] (LoRA folded)
__device__ float g_Q[(size_t)ROWS*AINNER];
__device__ float g_K[(size_t)ROWS*DHEAD];
__device__ float g_V[(size_t)ROWS*DHEAD];
__device__ __align__(16) __half g_AC16[(size_t)ROWS*KC];       // [attn | ff] fp16
__device__ __align__(16) __half g_WC16[(size_t)DIMX*KC];       // [n][kc] (LoRA folded)
__device__ __align__(8) float2 g_RT[NSEQ*32];                  // (cos, sin) table

// ---------------- small helpers ----------------
__device__ __forceinline__ uint32_t smem_u32(const void* p) {
    uint32_t a;
    asm("{ .reg .u64 t; cvta.to.shared.u64 t, %1; cvt.u32.u64 %0, t; }" : "=r"(a) : "l"(p));
    return a;
}
__device__ __forceinline__ void cp16(uint32_t saddr, const void* g) {
    asm volatile("cp.async.cg.shared.global [%0], [%1], 16;" :: "r"(saddr), "l"(g) : "memory");
}
__device__ __forceinline__ void mma_f16(float* d, const uint32_t* a, const uint32_t* b) {
    asm volatile(
        "mma.sync.aligned.m16n8k16.row.col.f32.f16.f16.f32 "
        "{%0,%1,%2,%3}, {%4,%5,%6,%7}, {%8,%9}, {%0,%1,%2,%3};"
        : "+f"(d[0]), "+f"(d[1]), "+f"(d[2]), "+f"(d[3])
        : "r"(a[0]), "r"(a[1]), "r"(a[2]), "r"(a[3]), "r"(b[0]), "r"(b[1]));
}
__device__ __forceinline__ uint32_t pack_h2(float lo, float hi) {
    __half2 h = __floats2half2_rn(lo, hi);
    return *(uint32_t*)&h;
}

// ================= shared GEMM mainloop =================
#define HGS 4
#define HROW 20
#define HSTW (256*HROW)
#define HGSMEM (HGS*HSTW*4)     // 81920 bytes

#define GEMM_MAINLOOP(A_, B_, K_)                                              \
    extern __shared__ float smemf[];                                           \
    uint32_t* sm32 = (uint32_t*)smemf;                                         \
    const int tid = threadIdx.x;                                               \
    const int wid = tid >> 5, lane = tid & 31;                                 \
    const int gq = lane >> 2, tg = lane & 3;                                   \
    const int wm = (wid & 3) * 32, wn = (wid >> 2) * 64;                       \
    const int m0 = blockIdx.x * 128, n0 = blockIdx.y * 128;                    \
    const __half* Ag = (A_) + (size_t)m0 * (K_);                               \
    const __half* Bg = (B_) + (size_t)n0 * (K_);                               \
    const uint32_t sb = smem_u32(smemf);                                       \
    const int lrow = tid >> 1;                                                 \
    const int lp = (tid & 1) * 2;                                              \
    const int NK = (K_) >> 5;                                                  \
    auto load_stage = [&](int kt, int s) {                                     \
        const uint32_t sa = sb + s * HSTW * 4;                                 \
        const uint32_t sB = sa + 128 * HROW * 4;                               \
        const __half* ag = Ag + (size_t)lrow * (K_) + kt * 32;                 \
        const __half* bg = Bg + (size_t)lrow * (K_) + kt * 32;                 \
        _Pragma("unroll")                                                      \
        for (int i = 0; i < 2; i++) {                                          \
            int p = lp + i;                                                    \
            uint32_t off = (lrow * HROW + p * 4) * 4;                          \
            cp16(sa + off, ag + p * 8);                                        \
            cp16(sB + off, bg + p * 8);                                        \
        }                                                                      \
    };                                                                         \
    float acc[2][8][4];                                                        \
    _Pragma("unroll")                                                          \
    for (int mt = 0; mt < 2; mt++)                                             \
        for (int nt = 0; nt < 8; nt++)                                         \
            for (int i = 0; i < 4; i++) acc[mt][nt][i] = 0.f;                  \
    _Pragma("unroll")                                                          \
    for (int p = 0; p < 3; p++) {                                              \
        load_stage(p, p);                                                      \
        asm volatile("cp.async.commit_group;" ::: "memory");                   \
    }                                                                          \
    _Pragma("unroll 1")                                                        \
    for (int kt = 0; kt < NK; kt++) {                                          \
        asm volatile("cp.async.wait_group 2;" ::: "memory");                   \
        __syncthreads();                                                       \
        if (kt + 3 < NK) load_stage(kt + 3, (kt + 3) & 3);                     \
        asm volatile("cp.async.commit_group;" ::: "memory");                   \
        const int s = kt & 3;                                                  \
        const uint32_t* As = sm32 + s * HSTW;                                  \
        const uint32_t* Bs = As + 128 * HROW;                                  \
        _Pragma("unroll")                                                      \
        for (int ks = 0; ks < 2; ks++) {                                       \
            uint32_t a[2][4], b[8][2];                                         \
            _Pragma("unroll")                                                  \
            for (int mt = 0; mt < 2; mt++) {                                   \
                int r = wm + mt * 16 + gq;                                     \
                a[mt][0] = As[r * HROW + ks * 8 + tg];                         \
                a[mt][1] = As[(r + 8) * HROW + ks * 8 + tg];                   \
                a[mt][2] = As[r * HROW + ks * 8 + tg + 4];                     \
                a[mt][3] = As[(r + 8) * HROW + ks * 8 + tg + 4];               \
            }                                                                  \
            _Pragma("unroll")                                                  \
            for (int nt = 0; nt < 8; nt++) {                                   \
                int n = wn + nt * 8 + gq;                                      \
                b[nt][0] = Bs[n * HROW + ks * 8 + tg];                         \
                b[nt][1] = Bs[n * HROW + ks * 8 + tg + 4];                     \
            }                                                                  \
            _Pragma("unroll")                                                  \
            for (int mt = 0; mt < 2; mt++)                                     \
                for (int nt = 0; nt < 8; nt++)                                 \
                    mma_f16(acc[mt][nt], a[mt], b[nt]);                        \
        }                                                                      \
    }

// ---------------- out GEMM (lean epilogue) ----------------
__global__ __launch_bounds__(256, 2) void h_gemm_out(const __half* __restrict__ A,
                                                     const __half* __restrict__ Bt,
                                                     float* __restrict__ C,
                                                     int N, int K) {
    GEMM_MAINLOOP(A, Bt, K)
    const int rbase = m0 + wm + gq;
    const int cbase = n0 + wn + tg * 2;
#pragma unroll
    for (int mt = 0; mt < 2; mt++) {
#pragma unroll
        for (int nt = 0; nt < 8; nt++) {
            int r = rbase + mt * 16;
            int cc = cbase + nt * 8;
            *(float2*)(C + (size_t)r * N + cc) =
                make_float2(acc[mt][nt][0], acc[mt][nt][1]);
            *(float2*)(C + (size_t)(r + 8) * N + cc) =
                make_float2(acc[mt][nt][2], acc[mt][nt][3]);
        }
    }
}

// ---------------- fused GEMM (Q/K/V RoPE + ff silu epilogue) ----------------
__global__ __launch_bounds__(256, 2) void h_gemm_fused(const __half* __restrict__ A,
                                                       const __half* __restrict__ Bt,
                                                       float* __restrict__ Qg,
                                                       float* __restrict__ Kg,
                                                       float* __restrict__ Vg,
                                                       __half* __restrict__ Hc,
                                                       int K) {
    GEMM_MAINLOOP(A, Bt, K)
    const int rbase = m0 + wm + gq;
    const int cbase = n0 + wn + tg * 2;

    if (n0 >= JFF) {
#pragma unroll
        for (int mt = 0; mt < 2; mt++) {
#pragma unroll
            for (int nt = 0; nt < 8; nt++) {
                int r = rbase + mt * 16;
                int hc = (cbase + nt * 8 - JFF) >> 1;
                float x0 = acc[mt][nt][0], gg0 = acc[mt][nt][1];
                float x1 = acc[mt][nt][2], gg1 = acc[mt][nt][3];
                Hc[(size_t)r * KC + KOFF + hc]       = __float2half(x0 * gg0 / (1.f + __expf(-gg0)));
                Hc[(size_t)(r + 8) * KC + KOFF + hc] = __float2half(x1 * gg1 / (1.f + __expf(-gg1)));
            }
        }
    } else if (n0 < JK) {
        const int fi0 = (tg * 2) & 31;
#pragma unroll
        for (int mt = 0; mt < 2; mt++) {
#pragma unroll
            for (int e2 = 0; e2 < 2; e2++) {
                int r = rbase + mt * 16 + e2 * 8;
                const float2* rt = g_RT + (size_t)(r & (NSEQ - 1)) * 32;
#pragma unroll
                for (int nt = 0; nt < 8; nt++) {
                    int fi = (fi0 + nt * 8) & 31;
                    float2 cs0 = rt[fi], cs1 = rt[fi + 1];
                    float sgn = (nt < 4) ? -1.f : 1.f;
                    float v0 = acc[mt][nt][e2 * 2],     v1 = acc[mt][nt][e2 * 2 + 1];
                    float p0 = acc[mt][nt ^ 4][e2 * 2], p1 = acc[mt][nt ^ 4][e2 * 2 + 1];
                    float q0 = (v0 * cs0.x + sgn * p0 * cs0.y) * 0.125f;
                    float q1 = (v1 * cs1.x + sgn * p1 * cs1.y) * 0.125f;
                    *(float2*)(Qg + (size_t)r * AINNER + cbase + nt * 8) = make_float2(q0, q1);
                }
            }
        }
    } else if (wn == 0) {
        const int fi0 = (tg * 2) & 31;
#pragma unroll
        for (int mt = 0; mt < 2; mt++) {
#pragma unroll
            for (int e2 = 0; e2 < 2; e2++) {
                int r = rbase + mt * 16 + e2 * 8;
                const float2* rt = g_RT + (size_t)(r & (NSEQ - 1)) * 32;
#pragma unroll
                for (int nt = 0; nt < 8; nt++) {
                    int fi = (fi0 + nt * 8) & 31;
                    float2 cs0 = rt[fi], cs1 = rt[fi + 1];
                    float sgn = (nt < 4) ? -1.f : 1.f;
                    float v0 = acc[mt][nt][e2 * 2],     v1 = acc[mt][nt][e2 * 2 + 1];
                    float p0 = acc[mt][nt ^ 4][e2 * 2], p1 = acc[mt][nt ^ 4][e2 * 2 + 1];
                    float k0 = v0 * cs0.x + sgn * p0 * cs0.y;
                    float k1 = v1 * cs1.x + sgn * p1 * cs1.y;
                    int d = nt * 8 + tg * 2;
                    *(float2*)(Kg + (size_t)r * DHEAD + d) = make_float2(k0, k1);
                }
            }
        }
    } else {
#pragma unroll
        for (int mt = 0; mt < 2; mt++) {
#pragma unroll
            for (int nt = 0; nt < 8; nt++) {
                int r = rbase + mt * 16;
                int d = nt * 8 + tg * 2;
                *(float2*)(Vg + (size_t)r * DHEAD + d) =
                    make_float2(acc[mt][nt][0], acc[mt][nt][1]);
                *(float2*)(Vg + (size_t)(r + 8) * DHEAD + d) =
                    make_float2(acc[mt][nt][2], acc[mt][nt][3]);
            }
        }
    }
}

// ---------------- RoPE table ----------------
__global__ void rope_table(float2* __restrict__ rt) {
    int idx = blockIdx.x * 256 + threadIdx.x;
    int n = idx >> 5, fi = idx & 31;
    const float LNF = 9.2103403719761836f / 32.f;
    float freq = (float)n * __expf(-(float)fi * LNF);
    rt[idx] = make_float2(cosf(freq), sinf(freq));
}

// ---------------- weight transpose + fp16 + optional LoRA fold ----------
__global__ void w_t16s(const float* __restrict__ in, __half* __restrict__ out,
                       int Kd, int Nd, int ostride, int ooff,
                       const float* __restrict__ la, const float* __restrict__ lb) {
    __shared__ float t[32][33];
    int k0 = blockIdx.y * 32, n0 = blockIdx.x * 32;
    int tx = threadIdx.x, ty = threadIdx.y;
#pragma unroll
    for (int i = 0; i < 4; i++) {
        int k = k0 + ty + 8 * i;
        int n = n0 + tx;
        float val = in[(size_t)k * Nd + n];
        if (la) {
#pragma unroll
            for (int r = 0; r < 8; r++)
                val += la[k * 8 + r] * lb[r * Nd + n];
        }
        t[ty + 8 * i][tx] = val;
    }
    __syncthreads();
#pragma unroll
    for (int i = 0; i < 4; i++)
        out[(size_t)(n0 + ty + 8 * i) * ostride + ooff + k0 + tx] = __float2half(t[tx][ty + 8 * i]);
}

__global__ void w_t16_perm(const float* __restrict__ in, __half* __restrict__ out,
                           const float* __restrict__ aq, const float* __restrict__ bq,
                           const float* __restrict__ ak, const float* __restrict__ bk,
                           const float* __restrict__ av, const float* __restrict__ bv) {
    __shared__ float t[32][33];
    int k0 = blockIdx.y * 32, n0 = blockIdx.x * 32;
    int tx = threadIdx.x, ty = threadIdx.y;
#pragma unroll
    for (int i = 0; i < 4; i++) {
        int k = k0 + ty + 8 * i;
        int j = n0 + tx;
        float val;
        if (j < JK) {
            val = in[(size_t)k * FUSEDC + j];
#pragma unroll
            for (int r = 0; r < 8; r++) val += aq[k * 8 + r] * bq[r * AINNER + j];
        } else if (j < JV) {
            val = in[(size_t)k * FUSEDC + j];
            int d = j - JK;
#pragma unroll
            for (int r = 0; r < 8; r++) val += ak[k * 8 + r] * bk[r * DHEAD + d];
        } else if (j < JFF) {
            val = in[(size_t)k * FUSEDC + j];
            int d = j - JV;
#pragma unroll
            for (int r = 0; r < 8; r++) val += av[k * 8 + r] * bv[r * DHEAD + d];
        } else {
            int p = j - JFF;
            val = in[(size_t)k * FUSEDC + I2 + (p >> 1) + (p & 1) * FFINNER];
        }
        t[ty + 8 * i][tx] = val;
    }
    __syncthreads();
#pragma unroll
    for (int i = 0; i < 4; i++)
        out[(size_t)(n0 + ty + 8 * i) * DIMX + k0 + tx] = __float2half(t[tx][ty + 8 * i]);
}

// ---------------- layernorm (fp16 out) ----------------
__global__ void ln_kernel(const float* __restrict__ x, const float* __restrict__ gamma,
                          __half* __restrict__ xn16) {
    int row = blockIdx.x;
    const float* xr = x + (size_t)row * DIMX;
    float s = 0.f, s2 = 0.f;
    for (int i = threadIdx.x; i < DIMX; i += 256) { float v = xr[i]; s += v; s2 += v * v; }
    for (int o = 16; o > 0; o >>= 1) {
        s  += __shfl_xor_sync(0xffffffff, s,  o);
        s2 += __shfl_xor_sync(0xffffffff, s2, o);
    }
    __shared__ float sh[16];
    int wid = threadIdx.x >> 5, lane = threadIdx.x & 31;
    if (lane == 0) { sh[wid] = s; sh[8 + wid] = s2; }
    __syncthreads();
    if (threadIdx.x == 0) {
        float S = 0.f, S2 = 0.f;
        for (int w = 0; w < 8; w++) { S += sh[w]; S2 += sh[8 + w]; }
        sh[0] = S; sh[8] = S2;
    }
    __syncthreads();
    float mu = sh[0] * (1.f / DIMX);
    float var = sh[8] * (1.f / DIMX) - mu * mu;
    float inv = rsqrtf(var + 1e-5f);
    __half* o16 = xn16 + (size_t)row * DIMX;
    for (int i = threadIdx.x; i < DIMX; i += 256)
        o16[i] = __float2half((xr[i] - mu) * inv * gamma[i]);
}

// ================= fp16 MMA flash attention, 128-row Q tile ======
// 256 threads (8 warps x 16 q-rows). K/V chunk = 64 keys.
#define QS_W (128*68)                // 8704 floats
#define KROW 36
#define VROW 72
#define ATTN_SMEM ((QS_W + 64*KROW*2 + 32*VROW)*4)   // 62464 B

__global__ __launch_bounds__(256) void attn_mma(const float* __restrict__ Qg,
                                                const float* __restrict__ Kg,
                                                const float* __restrict__ Vg,
                                                __half* __restrict__ O16) {
    extern __shared__ float sm[];
    float* Qs = sm;
    uint32_t* Kh = (uint32_t*)(sm + QS_W);
    uint32_t* Kl = Kh + 64 * KROW;
    uint32_t* Vp = Kl + 64 * KROW;

    const int tid = threadIdx.x, wid = tid >> 5, lane = tid & 31;
    const int gq = lane >> 2, tq = lane & 3;
    const int qt = gridDim.x - 1 - blockIdx.x;     // heavy tiles first
    const int h = blockIdx.y, b = blockIdx.z;
    const int q0 = qt * 128;

    // stage Q tile [128 q x 64 d]
    for (int i = tid; i < 2048; i += 256) {
        int r = i >> 4, d4 = (i & 15) * 4;
        *(float4*)(Qs + r * 68 + d4) =
            *(const float4*)(Qg + (size_t)(b * NSEQ + q0 + r) * AINNER + h * 64 + d4);
    }
    __syncthreads();

    uint32_t qh[4][4], ql[4][4];
#pragma unroll
    for (int c = 0; c < 4; c++) {
#pragma unroll
        for (int e = 0; e < 4; e++) {
            int rr = wid * 16 + gq + (e & 1) * 8;
            int cc = c * 16 + (e >> 1) * 8 + 2 * tq;
            float v0 = Qs[rr * 68 + cc], v1 = Qs[rr * 68 + cc + 1];
            __half h0 = __float2half_rn(v0), h1 = __float2half_rn(v1);
            __half2 hh = __halves2half2(h0, h1);
            qh[c][e] = *(uint32_t*)&hh;
            __half l0 = __float2half_rn(v0 - __half2float(h0));
            __half l1 = __float2half_rn(v1 - __half2float(h1));
            __half2 ll = __halves2half2(l0, l1);
            ql[c][e] = *(uint32_t*)&ll;
        }
    }

    float o[8][4];
#pragma unroll
    for (int nt = 0; nt < 8; nt++)
#pragma unroll
        for (int e = 0; e < 4; e++) o[nt][e] = 0.f;
    float m0 = -FLT_MAX, m1 = -FLT_MAX, l0s = 0.f, l1s = 0.f;

    const float* Kb = Kg + (size_t)b * NSEQ * DHEAD;
    const float* Vb = Vg + (size_t)b * NSEQ * DHEAD;

    for (int j0 = 0; j0 <= q0 + 64; j0 += 64) {
        __syncthreads();
        // load K (hi/lo fp16) and V (pair-packed fp16): 64 rows x 16 float4
        for (int i = tid; i < 1024; i += 256) {
            int r = i >> 4, d4 = (i & 15) * 4;
            float4 kv = *(const float4*)(Kb + (size_t)(j0 + r) * DHEAD + d4);
            __half h0 = __float2half_rn(kv.x), h1 = __float2half_rn(kv.y);
            __half h2 = __float2half_rn(kv.z), h3 = __float2half_rn(kv.w);
            __half2 p01 = __halves2half2(h0, h1), p23 = __halves2half2(h2, h3);
            Kh[r * KROW + d4 / 2]     = *(uint32_t*)&p01;
            Kh[r * KROW + d4 / 2 + 1] = *(uint32_t*)&p23;
            __half2 l01 = __halves2half2(__float2half_rn(kv.x - __half2float(h0)),
                                         __float2half_rn(kv.y - __half2float(h1)));
            __half2 l23 = __halves2half2(__float2half_rn(kv.z - __half2float(h2)),
                                         __float2half_rn(kv.w - __half2float(h3)));
            Kl[r * KROW + d4 / 2]     = *(uint32_t*)&l01;
            Kl[r * KROW + d4 / 2 + 1] = *(uint32_t*)&l23;

            float4 vv = *(const float4*)(Vb + (size_t)(j0 + r) * DHEAD + d4);
            __half* vh = (__half*)Vp;
            int p = r >> 1, half_sel = r & 1;
            vh[(p * VROW + d4) * 2 + half_sel]       = __float2half_rn(vv.x);
            vh[(p * VROW + d4 + 1) * 2 + half_sel]   = __float2half_rn(vv.y);
            vh[(p * VROW + d4 + 2) * 2 + half_sel]   = __float2half_rn(vv.z);
            vh[(p * VROW + d4 + 3) * 2 + half_sel]   = __float2half_rn(vv.w);
        }
        __syncthreads();

        float s[8][4];
#pragma unroll
        for (int nt = 0; nt < 8; nt++) {
            s[nt][0] = s[nt][1] = s[nt][2] = s[nt][3] = 0.f;
            const uint32_t* khr = Kh + (nt * 8 + gq) * KROW;
            const uint32_t* klr = Kl + (nt * 8 + gq) * KROW;
#pragma unroll
            for (int c = 0; c < 4; c++) {
                uint32_t bh[2] = { khr[c * 8 + tq], khr[c * 8 + 4 + tq] };
                uint32_t bl[2] = { klr[c * 8 + tq], klr[c * 8 + 4 + tq] };
                mma_f16(s[nt], qh[c], bh);
                mma_f16(s[nt], ql[c], bh);
                mma_f16(s[nt], qh[c], bl);
            }
        }

        // causal mask for the two diagonal chunks (global index compare)
        if (j0 >= q0) {
            int r0 = q0 + wid * 16 + gq, r1 = r0 + 8;
#pragma unroll
            for (int nt = 0; nt < 8; nt++) {
                int jc = j0 + nt * 8 + 2 * tq;
                if (jc     > r0) s[nt][0] = -1e30f;
                if (jc + 1 > r0) s[nt][1] = -1e30f;
                if (jc     > r1) s[nt][2] = -1e30f;
                if (jc + 1 > r1) s[nt][3] = -1e30f;
            }
        }

        float rx0 = -1e30f, rx1 = -1e30f;
#pragma unroll
        for (int nt = 0; nt < 8; nt++) {
            rx0 = fmaxf(rx0, fmaxf(s[nt][0], s[nt][1]));
            rx1 = fmaxf(rx1, fmaxf(s[nt][2], s[nt][3]));
        }
        rx0 = fmaxf(rx0, __shfl_xor_sync(0xffffffff, rx0, 1));
        rx0 = fmaxf(rx0, __shfl_xor_sync(0xffffffff, rx0, 2));
        rx1 = fmaxf(rx1, __shfl_xor_sync(0xffffffff, rx1, 1));
        rx1 = fmaxf(rx1, __shfl_xor_sync(0xffffffff, rx1, 2));
        float mn0 = fmaxf(m0, rx0), mn1 = fmaxf(m1, rx1);
        float c0 = __expf(m0 - mn0), c1 = __expf(m1 - mn1);
        float ps0 = 0.f, ps1 = 0.f;
#pragma unroll
        for (int nt = 0; nt < 8; nt++) {
            s[nt][0] = __expf(s[nt][0] - mn0);
            s[nt][1] = __expf(s[nt][1] - mn0);
            s[nt][2] = __expf(s[nt][2] - mn1);
            s[nt][3] = __expf(s[nt][3] - mn1);
            ps0 += s[nt][0] + s[nt][1];
            ps1 += s[nt][2] + s[nt][3];
        }
        ps0 += __shfl_xor_sync(0xffffffff, ps0, 1);
        ps0 += __shfl_xor_sync(0xffffffff, ps0, 2);
        ps1 += __shfl_xor_sync(0xffffffff, ps1, 1);
        ps1 += __shfl_xor_sync(0xffffffff, ps1, 2);
        l0s = l0s * c0 + ps0;
        l1s = l1s * c1 + ps1;
#pragma unroll
        for (int nt = 0; nt < 8; nt++) {
            o[nt][0] *= c0; o[nt][1] *= c0;
            o[nt][2] *= c1; o[nt][3] *= c1;
        }
        m0 = mn0; m1 = mn1;

        uint32_t ap[4][4];
#pragma unroll
        for (int kc = 0; kc < 4; kc++) {
            ap[kc][0] = pack_h2(s[2 * kc][0],     s[2 * kc][1]);
            ap[kc][1] = pack_h2(s[2 * kc][2],     s[2 * kc][3]);
            ap[kc][2] = pack_h2(s[2 * kc + 1][0], s[2 * kc + 1][1]);
            ap[kc][3] = pack_h2(s[2 * kc + 1][2], s[2 * kc + 1][3]);
        }

#pragma unroll
        for (int nt = 0; nt < 8; nt++) {
            int d = nt * 8 + gq;
#pragma unroll
            for (int kc = 0; kc < 4; kc++) {
                uint32_t bv[2] = { Vp[(kc * 8 + tq) * VROW + d],
                                   Vp[(kc * 8 + 4 + tq) * VROW + d] };
                mma_f16(o[nt], ap[kc], bv);
            }
        }
    }

    float il0 = 1.f / l0s, il1 = 1.f / l1s;
    int rg0 = b * NSEQ + q0 + wid * 16 + gq;
#pragma unroll
    for (int nt = 0; nt < 8; nt++) {
        int col = h * 64 + nt * 8 + 2 * tq;
        *(__half2*)(O16 + (size_t)rg0 * KC + col) =
            __floats2half2_rn(o[nt][0] * il0, o[nt][1] * il0);
        *(__half2*)(O16 + (size_t)(rg0 + 8) * KC + col) =
            __floats2half2_rn(o[nt][2] * il1, o[nt][3] * il1);
    }
}

// ---------------- launch ----------------
extern "C" void kernel_launch(void* const* d_in, const int* in_sizes, int n_in,
                              void* d_out, int out_size) {
    const float* x          = (const float*)d_in[0];
    const float* gamma      = (const float*)d_in[1];
    const float* w_fused    = (const float*)d_in[2];
    const float* w_attn_out = (const float*)d_in[3];
    const float* w_ff_out   = (const float*)d_in[4];
    const float* a_q        = (const float*)d_in[5];
    const float* b_q        = (const float*)d_in[6];
    const float* a_k        = (const float*)d_in[7];
    const float* b_k        = (const float*)d_in[8];
    const float* a_v        = (const float*)d_in[9];
    const float* b_v        = (const float*)d_in[10];
    const float* a_o        = (const float*)d_in[11];
    const float* b_o        = (const float*)d_in[12];
    float* out = (float*)d_out;

    float *Q, *K, *V;
    float2* RT;
    __half *XN16, *WF16, *AC16, *WC16;
    cudaGetSymbolAddress((void**)&XN16, g_XN16);
    cudaGetSymbolAddress((void**)&WF16, g_WF16);
    cudaGetSymbolAddress((void**)&Q, g_Q);
    cudaGetSymbolAddress((void**)&K, g_K);
    cudaGetSymbolAddress((void**)&V, g_V);
    cudaGetSymbolAddress((void**)&AC16, g_AC16);
    cudaGetSymbolAddress((void**)&WC16, g_WC16);
    cudaGetSymbolAddress((void**)&RT, g_RT);

    cudaFuncSetAttribute(h_gemm_fused, cudaFuncAttributeMaxDynamicSharedMemorySize, HGSMEM);
    cudaFuncSetAttribute(h_gemm_out, cudaFuncAttributeMaxDynamicSharedMemorySize, HGSMEM);
    cudaFuncSetAttribute(attn_mma, cudaFuncAttributeMaxDynamicSharedMemorySize, ATTN_SMEM);

    // prep
    rope_table<<<(NSEQ * 32) / 256, 256>>>(RT);
    w_t16_perm<<<dim3(FPAD2 / 32, DIMX / 32), dim3(32, 8)>>>(w_fused, WF16,
                                                             a_q, b_q, a_k, b_k, a_v, b_v);
    w_t16s<<<dim3(DIMX / 32, AINNER / 32), dim3(32, 8)>>>(w_attn_out, WC16, AINNER, DIMX, KC, 0,
                                                          a_o, b_o);
    w_t16s<<<dim3(DIMX / 32, FFINNER / 32), dim3(32, 8)>>>(w_ff_out, WC16, FFINNER, DIMX, KC, KOFF,
                                                           nullptr, nullptr);

    ln_kernel<<<ROWS, 256>>>(x, gamma, XN16);
    h_gemm_fused<<<dim3(ROWS / 128, FPAD2 / 128), 256, HGSMEM>>>(XN16, WF16, Q, K, V, AC16, DIMX);
    attn_mma<<<dim3(NSEQ / 128, HEADS, BATCH), 256, ATTN_SMEM>>>(Q, K, V, AC16);
    h_gemm_out<<<dim3(ROWS / 128, DIMX / 128), 256, HGSMEM>>>(AC16, WC16, out, DIMX, KC);
}

// round 16
// speedup vs baseline: 1.0134x; 1.0134x over previous
#include <cuda_runtime.h>
#include <cuda_fp16.h>
#include <math.h>
#include <float.h>
#include <stdint.h>

// ---------------- problem constants ----------------
#define DIMX 2048
#define NSEQ 2048
#define BATCH 2
#define HEADS 16
#define DHEAD 64
#define ROWS (BATCH*NSEQ)          // 4096
#define AINNER 1024
#define FFINNER 8192
#define FUSEDC 17536
#define FPAD2 17536                // [Q 1024 | K 64 | V 64 | ff pairs 16384]
#define JK 1024
#define JV 1088
#define JFF 1152
#define I2 1152
#define KC 9216                    // combined K: 1024 (attn) + 8192 (ff)
#define KOFF 1024

// ---------------- scratch (device globals) --------
__device__ __align__(16) __half g_XN16[(size_t)ROWS*DIMX];
__device__ __align__(16) __half g_WF16[(size_t)FPAD2*DIMX];    // [n][k] (LoRA folded)
__device__ float g_Q[(size_t)ROWS*AINNER];
__device__ float g_K[(size_t)ROWS*DHEAD];
__device__ float g_V[(size_t)ROWS*DHEAD];
__device__ __align__(16) __half g_AC16[(size_t)ROWS*KC];       // [attn | ff] fp16
__device__ __align__(16) __half g_WC16[(size_t)DIMX*KC];       // [n][kc] (LoRA folded)
__device__ __align__(8) float2 g_RT[NSEQ*32];                  // (cos, sin) table

// ---------------- small helpers ----------------
__device__ __forceinline__ uint32_t smem_u32(const void* p) {
    uint32_t a;
    asm("{ .reg .u64 t; cvta.to.shared.u64 t, %1; cvt.u32.u64 %0, t; }" : "=r"(a) : "l"(p));
    return a;
}
__device__ __forceinline__ void cp16(uint32_t saddr, const void* g) {
    asm volatile("cp.async.cg.shared.global [%0], [%1], 16;" :: "r"(saddr), "l"(g) : "memory");
}
__device__ __forceinline__ void mma_f16(float* d, const uint32_t* a, const uint32_t* b) {
    asm volatile(
        "mma.sync.aligned.m16n8k16.row.col.f32.f16.f16.f32 "
        "{%0,%1,%2,%3}, {%4,%5,%6,%7}, {%8,%9}, {%0,%1,%2,%3};"
        : "+f"(d[0]), "+f"(d[1]), "+f"(d[2]), "+f"(d[3])
        : "r"(a[0]), "r"(a[1]), "r"(a[2]), "r"(a[3]), "r"(b[0]), "r"(b[1]));
}
__device__ __forceinline__ uint32_t pack_h2(float lo, float hi) {
    __half2 h = __floats2half2_rn(lo, hi);
    return *(uint32_t*)&h;
}

// ================= shared GEMM mainloop =================
#define HGS 4
#define HROW 20
#define HSTW (256*HROW)
#define HGSMEM (HGS*HSTW*4)     // 81920 bytes

#define GEMM_MAINLOOP(A_, B_, K_)                                              \
    extern __shared__ float smemf[];                                           \
    uint32_t* sm32 = (uint32_t*)smemf;                                         \
    const int tid = threadIdx.x;                                               \
    const int wid = tid >> 5, lane = tid & 31;                                 \
    const int gq = lane >> 2, tg = lane & 3;                                   \
    const int wm = (wid & 3) * 32, wn = (wid >> 2) * 64;                       \
    const int m0 = blockIdx.x * 128, n0 = blockIdx.y * 128;                    \
    const __half* Ag = (A_) + (size_t)m0 * (K_);                               \
    const __half* Bg = (B_) + (size_t)n0 * (K_);                               \
    const uint32_t sb = smem_u32(smemf);                                       \
    const int lrow = tid >> 1;                                                 \
    const int lp = (tid & 1) * 2;                                              \
    const int NK = (K_) >> 5;                                                  \
    auto load_stage = [&](int kt, int s) {                                     \
        const uint32_t sa = sb + s * HSTW * 4;                                 \
        const uint32_t sB = sa + 128 * HROW * 4;                               \
        const __half* ag = Ag + (size_t)lrow * (K_) + kt * 32;                 \
        const __half* bg = Bg + (size_t)lrow * (K_) + kt * 32;                 \
        _Pragma("unroll")                                                      \
        for (int i = 0; i < 2; i++) {                                          \
            int p = lp + i;                                                    \
            uint32_t off = (lrow * HROW + p * 4) * 4;                          \
            cp16(sa + off, ag + p * 8);                                        \
            cp16(sB + off, bg + p * 8);                                        \
        }                                                                      \
    };                                                                         \
    float acc[2][8][4];                                                        \
    _Pragma("unroll")                                                          \
    for (int mt = 0; mt < 2; mt++)                                             \
        for (int nt = 0; nt < 8; nt++)                                         \
            for (int i = 0; i < 4; i++) acc[mt][nt][i] = 0.f;                  \
    _Pragma("unroll")                                                          \
    for (int p = 0; p < 3; p++) {                                              \
        load_stage(p, p);                                                      \
        asm volatile("cp.async.commit_group;" ::: "memory");                   \
    }                                                                          \
    _Pragma("unroll 1")                                                        \
    for (int kt = 0; kt < NK; kt++) {                                          \
        asm volatile("cp.async.wait_group 2;" ::: "memory");                   \
        __syncthreads();                                                       \
        if (kt + 3 < NK) load_stage(kt + 3, (kt + 3) & 3);                     \
        asm volatile("cp.async.commit_group;" ::: "memory");                   \
        const int s = kt & 3;                                                  \
        const uint32_t* As = sm32 + s * HSTW;                                  \
        const uint32_t* Bs = As + 128 * HROW;                                  \
        _Pragma("unroll")                                                      \
        for (int ks = 0; ks < 2; ks++) {                                       \
            uint32_t a[2][4], b[8][2];                                         \
            _Pragma("unroll")                                                  \
            for (int mt = 0; mt < 2; mt++) {                                   \
                int r = wm + mt * 16 + gq;                                     \
                a[mt][0] = As[r * HROW + ks * 8 + tg];                         \
                a[mt][1] = As[(r + 8) * HROW + ks * 8 + tg];                   \
                a[mt][2] = As[r * HROW + ks * 8 + tg + 4];                     \
                a[mt][3] = As[(r + 8) * HROW + ks * 8 + tg + 4];               \
            }                                                                  \
            _Pragma("unroll")                                                  \
            for (int nt = 0; nt < 8; nt++) {                                   \
                int n = wn + nt * 8 + gq;                                      \
                b[nt][0] = Bs[n * HROW + ks * 8 + tg];                         \
                b[nt][1] = Bs[n * HROW + ks * 8 + tg + 4];                     \
            }                                                                  \
            _Pragma("unroll")                                                  \
            for (int mt = 0; mt < 2; mt++)                                     \
                for (int nt = 0; nt < 8; nt++)                                 \
                    mma_f16(acc[mt][nt], a[mt], b[nt]);                        \
        }                                                                      \
    }

// ---------------- out GEMM (lean epilogue) ----------------
__global__ __launch_bounds__(256, 2) void h_gemm_out(const __half* __restrict__ A,
                                                     const __half* __restrict__ Bt,
                                                     float* __restrict__ C,
                                                     int N, int K) {
    GEMM_MAINLOOP(A, Bt, K)
    const int rbase = m0 + wm + gq;
    const int cbase = n0 + wn + tg * 2;
#pragma unroll
    for (int mt = 0; mt < 2; mt++) {
#pragma unroll
        for (int nt = 0; nt < 8; nt++) {
            int r = rbase + mt * 16;
            int cc = cbase + nt * 8;
            *(float2*)(C + (size_t)r * N + cc) =
                make_float2(acc[mt][nt][0], acc[mt][nt][1]);
            *(float2*)(C + (size_t)(r + 8) * N + cc) =
                make_float2(acc[mt][nt][2], acc[mt][nt][3]);
        }
    }
}

// ---------------- fused GEMM (Q/K/V RoPE + ff silu epilogue) ----------------
__global__ __launch_bounds__(256, 2) void h_gemm_fused(const __half* __restrict__ A,
                                                       const __half* __restrict__ Bt,
                                                       float* __restrict__ Qg,
                                                       float* __restrict__ Kg,
                                                       float* __restrict__ Vg,
                                                       __half* __restrict__ Hc,
                                                       int K) {
    GEMM_MAINLOOP(A, Bt, K)
    const int rbase = m0 + wm + gq;
    const int cbase = n0 + wn + tg * 2;

    if (n0 >= JFF) {
#pragma unroll
        for (int mt = 0; mt < 2; mt++) {
#pragma unroll
            for (int nt = 0; nt < 8; nt++) {
                int r = rbase + mt * 16;
                int hc = (cbase + nt * 8 - JFF) >> 1;
                float x0 = acc[mt][nt][0], gg0 = acc[mt][nt][1];
                float x1 = acc[mt][nt][2], gg1 = acc[mt][nt][3];
                Hc[(size_t)r * KC + KOFF + hc]       = __float2half(x0 * gg0 / (1.f + __expf(-gg0)));
                Hc[(size_t)(r + 8) * KC + KOFF + hc] = __float2half(x1 * gg1 / (1.f + __expf(-gg1)));
            }
        }
    } else if (n0 < JK) {
        const int fi0 = (tg * 2) & 31;
#pragma unroll
        for (int mt = 0; mt < 2; mt++) {
#pragma unroll
            for (int e2 = 0; e2 < 2; e2++) {
                int r = rbase + mt * 16 + e2 * 8;
                const float2* rt = g_RT + (size_t)(r & (NSEQ - 1)) * 32;
#pragma unroll
                for (int nt = 0; nt < 8; nt++) {
                    int fi = (fi0 + nt * 8) & 31;
                    float2 cs0 = rt[fi], cs1 = rt[fi + 1];
                    float sgn = (nt < 4) ? -1.f : 1.f;
                    float v0 = acc[mt][nt][e2 * 2],     v1 = acc[mt][nt][e2 * 2 + 1];
                    float p0 = acc[mt][nt ^ 4][e2 * 2], p1 = acc[mt][nt ^ 4][e2 * 2 + 1];
                    float q0 = (v0 * cs0.x + sgn * p0 * cs0.y) * 0.125f;
                    float q1 = (v1 * cs1.x + sgn * p1 * cs1.y) * 0.125f;
                    *(float2*)(Qg + (size_t)r * AINNER + cbase + nt * 8) = make_float2(q0, q1);
                }
            }
        }
    } else if (wn == 0) {
        const int fi0 = (tg * 2) & 31;
#pragma unroll
        for (int mt = 0; mt < 2; mt++) {
#pragma unroll
            for (int e2 = 0; e2 < 2; e2++) {
                int r = rbase + mt * 16 + e2 * 8;
                const float2* rt = g_RT + (size_t)(r & (NSEQ - 1)) * 32;
#pragma unroll
                for (int nt = 0; nt < 8; nt++) {
                    int fi = (fi0 + nt * 8) & 31;
                    float2 cs0 = rt[fi], cs1 = rt[fi + 1];
                    float sgn = (nt < 4) ? -1.f : 1.f;
                    float v0 = acc[mt][nt][e2 * 2],     v1 = acc[mt][nt][e2 * 2 + 1];
                    float p0 = acc[mt][nt ^ 4][e2 * 2], p1 = acc[mt][nt ^ 4][e2 * 2 + 1];
                    float k0 = v0 * cs0.x + sgn * p0 * cs0.y;
                    float k1 = v1 * cs1.x + sgn * p1 * cs1.y;
                    int d = nt * 8 + tg * 2;
                    *(float2*)(Kg + (size_t)r * DHEAD + d) = make_float2(k0, k1);
                }
            }
        }
    } else {
#pragma unroll
        for (int mt = 0; mt < 2; mt++) {
#pragma unroll
            for (int nt = 0; nt < 8; nt++) {
                int r = rbase + mt * 16;
                int d = nt * 8 + tg * 2;
                *(float2*)(Vg + (size_t)r * DHEAD + d) =
                    make_float2(acc[mt][nt][0], acc[mt][nt][1]);
                *(float2*)(Vg + (size_t)(r + 8) * DHEAD + d) =
                    make_float2(acc[mt][nt][2], acc[mt][nt][3]);
            }
        }
    }
}

// ================= combined prep: rope | ln | w_fused perm | w_attn | w_ff ==
// one launch, blocks dispatched by linear range -> phases overlap on chip.
#define NB_ROPE 256
#define NB_LN ROWS
#define NB_PERM ((FPAD2/32)*(DIMX/32))     // 548*64 = 35072
#define NB_WAO ((DIMX/32)*(AINNER/32))     // 64*32 = 2048
#define NB_WFF ((DIMX/32)*(FFINNER/32))    // 64*256 = 16384
#define B0 NB_ROPE
#define B1 (B0+NB_LN)
#define B2 (B1+NB_PERM)
#define B3 (B2+NB_WAO)
#define NB_ALL (B3+NB_WFF)

__global__ __launch_bounds__(256) void prep_all(
    const float* __restrict__ x, const float* __restrict__ gamma,
    const float* __restrict__ w_fused,
    const float* __restrict__ w_attn_out, const float* __restrict__ w_ff_out,
    const float* __restrict__ aq, const float* __restrict__ bq,
    const float* __restrict__ ak, const float* __restrict__ bk,
    const float* __restrict__ av, const float* __restrict__ bv,
    const float* __restrict__ ao, const float* __restrict__ bo,
    __half* __restrict__ xn16, __half* __restrict__ wf16,
    __half* __restrict__ wc16, float2* __restrict__ rt) {
    __shared__ float t[32][33];
    __shared__ float sh[16];
    const int bid = blockIdx.x;
    const int tid = threadIdx.x;
    const int tx = tid & 31, ty = tid >> 5;

    if (bid < B0) {
        // ---- rope table ----
        int idx = bid * 256 + tid;
        int n = idx >> 5, fi = idx & 31;
        const float LNF = 9.2103403719761836f / 32.f;
        float freq = (float)n * __expf(-(float)fi * LNF);
        rt[idx] = make_float2(cosf(freq), sinf(freq));
    } else if (bid < B1) {
        // ---- layernorm ----
        int row = bid - B0;
        const float* xr = x + (size_t)row * DIMX;
        float s = 0.f, s2 = 0.f;
        for (int i = tid; i < DIMX; i += 256) { float v = xr[i]; s += v; s2 += v * v; }
        for (int o = 16; o > 0; o >>= 1) {
            s  += __shfl_xor_sync(0xffffffff, s,  o);
            s2 += __shfl_xor_sync(0xffffffff, s2, o);
        }
        int wd = tid >> 5, lane = tid & 31;
        if (lane == 0) { sh[wd] = s; sh[8 + wd] = s2; }
        __syncthreads();
        if (tid == 0) {
            float S = 0.f, S2 = 0.f;
            for (int w = 0; w < 8; w++) { S += sh[w]; S2 += sh[8 + w]; }
            sh[0] = S; sh[8] = S2;
        }
        __syncthreads();
        float mu = sh[0] * (1.f / DIMX);
        float var = sh[8] * (1.f / DIMX) - mu * mu;
        float inv = rsqrtf(var + 1e-5f);
        __half* o16 = xn16 + (size_t)row * DIMX;
        for (int i = tid; i < DIMX; i += 256)
            o16[i] = __float2half((xr[i] - mu) * inv * gamma[i]);
    } else if (bid < B2) {
        // ---- w_fused: transpose + permute + fp16, q/k/v LoRA folded ----
        int l = bid - B1;
        int n0 = (l % (FPAD2 / 32)) * 32;
        int k0 = (l / (FPAD2 / 32)) * 32;
#pragma unroll
        for (int i = 0; i < 4; i++) {
            int k = k0 + ty + 8 * i;
            int j = n0 + tx;
            float val;
            if (j < JK) {
                val = w_fused[(size_t)k * FUSEDC + j];
#pragma unroll
                for (int r = 0; r < 8; r++) val += aq[k * 8 + r] * bq[r * AINNER + j];
            } else if (j < JV) {
                val = w_fused[(size_t)k * FUSEDC + j];
                int d = j - JK;
#pragma unroll
                for (int r = 0; r < 8; r++) val += ak[k * 8 + r] * bk[r * DHEAD + d];
            } else if (j < JFF) {
                val = w_fused[(size_t)k * FUSEDC + j];
                int d = j - JV;
#pragma unroll
                for (int r = 0; r < 8; r++) val += av[k * 8 + r] * bv[r * DHEAD + d];
            } else {
                int p = j - JFF;
                val = w_fused[(size_t)k * FUSEDC + I2 + (p >> 1) + (p & 1) * FFINNER];
            }
            t[ty + 8 * i][tx] = val;
        }
        __syncthreads();
#pragma unroll
        for (int i = 0; i < 4; i++)
            wf16[(size_t)(n0 + ty + 8 * i) * DIMX + k0 + tx] = __float2half(t[tx][ty + 8 * i]);
    } else if (bid < B3) {
        // ---- w_attn_out (+LoRA a_o b_o) -> WC16 cols [0,1024) ----
        int l = bid - B2;
        int n0 = (l % (DIMX / 32)) * 32;
        int k0 = (l / (DIMX / 32)) * 32;
#pragma unroll
        for (int i = 0; i < 4; i++) {
            int k = k0 + ty + 8 * i;
            int n = n0 + tx;
            float val = w_attn_out[(size_t)k * DIMX + n];
#pragma unroll
            for (int r = 0; r < 8; r++) val += ao[k * 8 + r] * bo[r * DIMX + n];
            t[ty + 8 * i][tx] = val;
        }
        __syncthreads();
#pragma unroll
        for (int i = 0; i < 4; i++)
            wc16[(size_t)(n0 + ty + 8 * i) * KC + k0 + tx] = __float2half(t[tx][ty + 8 * i]);
    } else {
        // ---- w_ff_out -> WC16 cols [1024,9216) ----
        int l = bid - B3;
        int n0 = (l % (DIMX / 32)) * 32;
        int k0 = (l / (DIMX / 32)) * 32;
#pragma unroll
        for (int i = 0; i < 4; i++) {
            int k = k0 + ty + 8 * i;
            int n = n0 + tx;
            t[ty + 8 * i][tx] = w_ff_out[(size_t)k * DIMX + n];
        }
        __syncthreads();
#pragma unroll
        for (int i = 0; i < 4; i++)
            wc16[(size_t)(n0 + ty + 8 * i) * KC + KOFF + k0 + tx] = __float2half(t[tx][ty + 8 * i]);
    }
}

// ================= fp16 MMA flash attention (R14 winner: 64-row Q tile) ====
#define QS_W (64*68)
#define KROW 36
#define VROW 72
#define ATTN_SMEM ((QS_W + 64*KROW*2 + 32*VROW)*4)   // 45056 B

__global__ __launch_bounds__(128) void attn_mma(const float* __restrict__ Qg,
                                                const float* __restrict__ Kg,
                                                const float* __restrict__ Vg,
                                                __half* __restrict__ O16) {
    extern __shared__ float sm[];
    float* Qs = sm;
    uint32_t* Kh = (uint32_t*)(sm + QS_W);
    uint32_t* Kl = Kh + 64 * KROW;
    uint32_t* Vp = Kl + 64 * KROW;

    const int tid = threadIdx.x, wid = tid >> 5, lane = tid & 31;
    const int gq = lane >> 2, tq = lane & 3;
    const int qt = gridDim.x - 1 - blockIdx.x;
    const int h = blockIdx.y, b = blockIdx.z;
    const int q0 = qt * 64;

    for (int i = tid; i < 1024; i += 128) {
        int r = i >> 4, d4 = (i & 15) * 4;
        *(float4*)(Qs + r * 68 + d4) =
            *(const float4*)(Qg + (size_t)(b * NSEQ + q0 + r) * AINNER + h * 64 + d4);
    }
    __syncthreads();

    uint32_t qh[4][4], ql[4][4];
#pragma unroll
    for (int c = 0; c < 4; c++) {
#pragma unroll
        for (int e = 0; e < 4; e++) {
            int rr = wid * 16 + gq + (e & 1) * 8;
            int cc = c * 16 + (e >> 1) * 8 + 2 * tq;
            float v0 = Qs[rr * 68 + cc], v1 = Qs[rr * 68 + cc + 1];
            __half h0 = __float2half_rn(v0), h1 = __float2half_rn(v1);
            __half2 hh = __halves2half2(h0, h1);
            qh[c][e] = *(uint32_t*)&hh;
            __half l0 = __float2half_rn(v0 - __half2float(h0));
            __half l1 = __float2half_rn(v1 - __half2float(h1));
            __half2 ll = __halves2half2(l0, l1);
            ql[c][e] = *(uint32_t*)&ll;
        }
    }

    float o[8][4];
#pragma unroll
    for (int nt = 0; nt < 8; nt++)
#pragma unroll
        for (int e = 0; e < 4; e++) o[nt][e] = 0.f;
    float m0 = -FLT_MAX, m1 = -FLT_MAX, l0s = 0.f, l1s = 0.f;

    const float* Kb = Kg + (size_t)b * NSEQ * DHEAD;
    const float* Vb = Vg + (size_t)b * NSEQ * DHEAD;

    for (int j0 = 0; j0 <= q0; j0 += 64) {
        __syncthreads();
        for (int i = tid; i < 1024; i += 128) {
            int r = i >> 4, d4 = (i & 15) * 4;
            float4 kv = *(const float4*)(Kb + (size_t)(j0 + r) * DHEAD + d4);
            __half h0 = __float2half_rn(kv.x), h1 = __float2half_rn(kv.y);
            __half h2 = __float2half_rn(kv.z), h3 = __float2half_rn(kv.w);
            __half2 p01 = __halves2half2(h0, h1), p23 = __halves2half2(h2, h3);
            Kh[r * KROW + d4 / 2]     = *(uint32_t*)&p01;
            Kh[r * KROW + d4 / 2 + 1] = *(uint32_t*)&p23;
            __half2 l01 = __halves2half2(__float2half_rn(kv.x - __half2float(h0)),
                                         __float2half_rn(kv.y - __half2float(h1)));
            __half2 l23 = __halves2half2(__float2half_rn(kv.z - __half2float(h2)),
                                         __float2half_rn(kv.w - __half2float(h3)));
            Kl[r * KROW + d4 / 2]     = *(uint32_t*)&l01;
            Kl[r * KROW + d4 / 2 + 1] = *(uint32_t*)&l23;

            float4 vv = *(const float4*)(Vb + (size_t)(j0 + r) * DHEAD + d4);
            __half* vh = (__half*)Vp;
            int p = r >> 1, half_sel = r & 1;
            vh[(p * VROW + d4) * 2 + half_sel]       = __float2half_rn(vv.x);
            vh[(p * VROW + d4 + 1) * 2 + half_sel]   = __float2half_rn(vv.y);
            vh[(p * VROW + d4 + 2) * 2 + half_sel]   = __float2half_rn(vv.z);
            vh[(p * VROW + d4 + 3) * 2 + half_sel]   = __float2half_rn(vv.w);
        }
        __syncthreads();

        float s[8][4];
#pragma unroll
        for (int nt = 0; nt < 8; nt++) {
            s[nt][0] = s[nt][1] = s[nt][2] = s[nt][3] = 0.f;
            const uint32_t* khr = Kh + (nt * 8 + gq) * KROW;
            const uint32_t* klr = Kl + (nt * 8 + gq) * KROW;
#pragma unroll
            for (int c = 0; c < 4; c++) {
                uint32_t bh[2] = { khr[c * 8 + tq], khr[c * 8 + 4 + tq] };
                uint32_t bl[2] = { klr[c * 8 + tq], klr[c * 8 + 4 + tq] };
                mma_f16(s[nt], qh[c], bh);
                mma_f16(s[nt], ql[c], bh);
                mma_f16(s[nt], qh[c], bl);
            }
        }

        if (j0 == q0) {
            int r0 = wid * 16 + gq, r1 = r0 + 8;
#pragma unroll
            for (int nt = 0; nt < 8; nt++) {
                int jc = nt * 8 + 2 * tq;
                if (jc     > r0) s[nt][0] = -1e30f;
                if (jc + 1 > r0) s[nt][1] = -1e30f;
                if (jc     > r1) s[nt][2] = -1e30f;
                if (jc + 1 > r1) s[nt][3] = -1e30f;
            }
        }

        float rx0 = -1e30f, rx1 = -1e30f;
#pragma unroll
        for (int nt = 0; nt < 8; nt++) {
            rx0 = fmaxf(rx0, fmaxf(s[nt][0], s[nt][1]));
            rx1 = fmaxf(rx1, fmaxf(s[nt][2], s[nt][3]));
        }
        rx0 = fmaxf(rx0, __shfl_xor_sync(0xffffffff, rx0, 1));
        rx0 = fmaxf(rx0, __shfl_xor_sync(0xffffffff, rx0, 2));
        rx1 = fmaxf(rx1, __shfl_xor_sync(0xffffffff, rx1, 1));
        rx1 = fmaxf(rx1, __shfl_xor_sync(0xffffffff, rx1, 2));
        float mn0 = fmaxf(m0, rx0), mn1 = fmaxf(m1, rx1);
        float c0 = __expf(m0 - mn0), c1 = __expf(m1 - mn1);
        float ps0 = 0.f, ps1 = 0.f;
#pragma unroll
        for (int nt = 0; nt < 8; nt++) {
            s[nt][0] = __expf(s[nt][0] - mn0);
            s[nt][1] = __expf(s[nt][1] - mn0);
            s[nt][2] = __expf(s[nt][2] - mn1);
            s[nt][3] = __expf(s[nt][3] - mn1);
            ps0 += s[nt][0] + s[nt][1];
            ps1 += s[nt][2] + s[nt][3];
        }
        ps0 += __shfl_xor_sync(0xffffffff, ps0, 1);
        ps0 += __shfl_xor_sync(0xffffffff, ps0, 2);
        ps1 += __shfl_xor_sync(0xffffffff, ps1, 1);
        ps1 += __shfl_xor_sync(0xffffffff, ps1, 2);
        l0s = l0s * c0 + ps0;
        l1s = l1s * c1 + ps1;
#pragma unroll
        for (int nt = 0; nt < 8; nt++) {
            o[nt][0] *= c0; o[nt][1] *= c0;
            o[nt][2] *= c1; o[nt][3] *= c1;
        }
        m0 = mn0; m1 = mn1;

        uint32_t ap[4][4];
#pragma unroll
        for (int kc = 0; kc < 4; kc++) {
            ap[kc][0] = pack_h2(s[2 * kc][0],     s[2 * kc][1]);
            ap[kc][1] = pack_h2(s[2 * kc][2],     s[2 * kc][3]);
            ap[kc][2] = pack_h2(s[2 * kc + 1][0], s[2 * kc + 1][1]);
            ap[kc][3] = pack_h2(s[2 * kc + 1][2], s[2 * kc + 1][3]);
        }

#pragma unroll
        for (int nt = 0; nt < 8; nt++) {
            int d = nt * 8 + gq;
#pragma unroll
            for (int kc = 0; kc < 4; kc++) {
                uint32_t bv[2] = { Vp[(kc * 8 + tq) * VROW + d],
                                   Vp[(kc * 8 + 4 + tq) * VROW + d] };
                mma_f16(o[nt], ap[kc], bv);
            }
        }
    }

    float il0 = 1.f / l0s, il1 = 1.f / l1s;
    int rg0 = b * NSEQ + q0 + wid * 16 + gq;
#pragma unroll
    for (int nt = 0; nt < 8; nt++) {
        int col = h * 64 + nt * 8 + 2 * tq;
        *(__half2*)(O16 + (size_t)rg0 * KC + col) =
            __floats2half2_rn(o[nt][0] * il0, o[nt][1] * il0);
        *(__half2*)(O16 + (size_t)(rg0 + 8) * KC + col) =
            __floats2half2_rn(o[nt][2] * il1, o[nt][3] * il1);
    }
}

// ---------------- launch ----------------
extern "C" void kernel_launch(void* const* d_in, const int* in_sizes, int n_in,
                              void* d_out, int out_size) {
    const float* x          = (const float*)d_in[0];
    const float* gamma      = (const float*)d_in[1];
    const float* w_fused    = (const float*)d_in[2];
    const float* w_attn_out = (const float*)d_in[3];
    const float* w_ff_out   = (const float*)d_in[4];
    const float* a_q        = (const float*)d_in[5];
    const float* b_q        = (const float*)d_in[6];
    const float* a_k        = (const float*)d_in[7];
    const float* b_k        = (const float*)d_in[8];
    const float* a_v        = (const float*)d_in[9];
    const float* b_v        = (const float*)d_in[10];
    const float* a_o        = (const float*)d_in[11];
    const float* b_o        = (const float*)d_in[12];
    float* out = (float*)d_out;

    float *Q, *K, *V;
    float2* RT;
    __half *XN16, *WF16, *AC16, *WC16;
    cudaGetSymbolAddress((void**)&XN16, g_XN16);
    cudaGetSymbolAddress((void**)&WF16, g_WF16);
    cudaGetSymbolAddress((void**)&Q, g_Q);
    cudaGetSymbolAddress((void**)&K, g_K);
    cudaGetSymbolAddress((void**)&V, g_V);
    cudaGetSymbolAddress((void**)&AC16, g_AC16);
    cudaGetSymbolAddress((void**)&WC16, g_WC16);
    cudaGetSymbolAddress((void**)&RT, g_RT);

    cudaFuncSetAttribute(h_gemm_fused, cudaFuncAttributeMaxDynamicSharedMemorySize, HGSMEM);
    cudaFuncSetAttribute(h_gemm_out, cudaFuncAttributeMaxDynamicSharedMemorySize, HGSMEM);
    cudaFuncSetAttribute(attn_mma, cudaFuncAttributeMaxDynamicSharedMemorySize, ATTN_SMEM);

    // combined prep (rope | ln | weight folds) — one launch, phases overlap
    prep_all<<<NB_ALL, 256>>>(x, gamma, w_fused, w_attn_out, w_ff_out,
                              a_q, b_q, a_k, b_k, a_v, b_v, a_o, b_o,
                              XN16, WF16, WC16, RT);

    h_gemm_fused<<<dim3(ROWS / 128, FPAD2 / 128), 256, HGSMEM>>>(XN16, WF16, Q, K, V, AC16, DIMX);
    attn_mma<<<dim3(NSEQ / 64, HEADS, BATCH), 128, ATTN_SMEM>>>(Q, K, V, AC16);
    h_gemm_out<<<dim3(ROWS / 128, DIMX / 128), 256, HGSMEM>>>(AC16, WC16, out, DIMX, KC);
}